// round 5
// baseline (speedup 1.0000x reference)
#include <cuda_runtime.h>
#include <cuda_bf16.h>

// MulticlassDice fused single-kernel version.
// dice[n][c] = (2*inter + 1e-5) / (cnt_in + cnt_tg + 1e-5)
// each_class_dice[c] = mean_n dice[n][c];  total = sum_c w[c]*each_class_dice[c]
// Output: [total, dice[0..7]] (verified rel_err=0 in R3).

#define NCLS 8
#define PIX (512 * 512)
#define MAXN 8
#define GX 64             // blocks per sample
#define NSLOT (3 * NCLS)  // 24: [in|tg|inter] x class

// Per-block partial histograms (unique slots -> no zeroing needed).
__device__ int g_partial[MAXN][GX][NSLOT];
__device__ unsigned int g_done;  // zero-initialized; last block resets to 0

__global__ __launch_bounds__(256) void k_dice_fused(const int* __restrict__ inB,
                                                    const int* __restrict__ tgB,
                                                    const float* __restrict__ w,
                                                    float* __restrict__ out,
                                                    int out_size, int N) {
    const int n = blockIdx.y;
    const int tid = threadIdx.x;

    // ---- per-block dtype detect (odd 32-bit words all zero => int64) ----
    __shared__ int s_is64;
    if (tid < 32) {
        int nz = 0;
#pragma unroll
        for (int i = 0; i < 8; i++) nz |= __ldg(&inB[2 * (tid + 32 * i) + 1]);
        unsigned mask = __ballot_sync(0xffffffffu, nz != 0);
        if (tid == 0) s_is64 = (mask == 0u) ? 1 : 0;
    }
    __syncthreads();
    const bool is64 = (s_is64 != 0);

    // ---- count ----
    int cin[NCLS], ctg[NCLS], cxx[NCLS];
#pragma unroll
    for (int c = 0; c < NCLS; c++) { cin[c] = 0; ctg[c] = 0; cxx[c] = 0; }

    const int stride = GX * 256;
    const int t0 = blockIdx.x * 256 + tid;

    if (is64) {
        // 2 pixels per int4 (low halves at .x and .z)
        const int4* a = (const int4*)inB + (size_t)n * (PIX / 2);
        const int4* b = (const int4*)tgB + (size_t)n * (PIX / 2);
        for (int i = t0; i < PIX / 2; i += stride) {
            int4 va = a[i], vb = b[i];
#pragma unroll
            for (int c = 0; c < NCLS; c++) {
                int a0 = (va.x == c), a1 = (va.z == c);
                int b0 = (vb.x == c), b1 = (vb.z == c);
                cin[c] += a0 + a1;
                ctg[c] += b0 + b1;
                cxx[c] += (a0 & b0) + (a1 & b1);
            }
        }
    } else {
        // 4 pixels per int4
        const int4* a = (const int4*)inB + (size_t)n * (PIX / 4);
        const int4* b = (const int4*)tgB + (size_t)n * (PIX / 4);
        for (int i = t0; i < PIX / 4; i += stride) {
            int4 va = a[i], vb = b[i];
#pragma unroll
            for (int c = 0; c < NCLS; c++) {
                int a0 = (va.x == c), a1 = (va.y == c), a2 = (va.z == c), a3 = (va.w == c);
                int b0 = (vb.x == c), b1 = (vb.y == c), b2 = (vb.z == c), b3 = (vb.w == c);
                cin[c] += a0 + a1 + a2 + a3;
                ctg[c] += b0 + b1 + b2 + b3;
                cxx[c] += (a0 & b0) + (a1 & b1) + (a2 & b2) + (a3 & b3);
            }
        }
    }

    // ---- warp reduce (REDUX.SUM) ----
#pragma unroll
    for (int c = 0; c < NCLS; c++) {
        cin[c] = __reduce_add_sync(0xffffffffu, cin[c]);
        ctg[c] = __reduce_add_sync(0xffffffffu, ctg[c]);
        cxx[c] = __reduce_add_sync(0xffffffffu, cxx[c]);
    }

    // ---- block reduce via smem, write partial to unique slot ----
    __shared__ int s[NSLOT];
    if (tid < NSLOT) s[tid] = 0;
    __syncthreads();
    if ((tid & 31) == 0) {
#pragma unroll
        for (int c = 0; c < NCLS; c++) {
            atomicAdd(&s[0 * NCLS + c], cin[c]);
            atomicAdd(&s[1 * NCLS + c], ctg[c]);
            atomicAdd(&s[2 * NCLS + c], cxx[c]);
        }
    }
    __syncthreads();
    if (tid < NSLOT) g_partial[n][blockIdx.x][tid] = s[tid];

    // ---- last-block-done epilogue ----
    __threadfence();  // release: partials visible before counter bump
    __shared__ bool s_last;
    if (tid == 0) {
        unsigned int prev = atomicAdd(&g_done, 1u);
        s_last = (prev == (unsigned int)(GX * N - 1));
    }
    __syncthreads();
    if (!s_last) return;

    __threadfence();  // acquire: all partials visible to last block

    __shared__ int cnt_s[MAXN][NSLOT];
    for (int p = tid; p < N * NSLOT; p += 256) {
        int nn = p / NSLOT, slot = p % NSLOT;
        int acc = 0;
#pragma unroll 8
        for (int b = 0; b < GX; b++) acc += g_partial[nn][b][slot];
        cnt_s[nn][slot] = acc;
    }
    __syncthreads();

    __shared__ float dice[MAXN][NCLS];
    __shared__ float mean_c[NCLS];
    __shared__ float total_s;
    if (tid < N * NCLS) {
        int nn = tid / NCLS, c = tid % NCLS;
        float inter = (float)cnt_s[nn][2 * NCLS + c];
        float sums = (float)(cnt_s[nn][0 * NCLS + c] + cnt_s[nn][1 * NCLS + c]);
        dice[nn][c] = (2.0f * inter + 1e-5f) / (sums + 1e-5f);
    }
    __syncthreads();
    if (tid < NCLS) {
        float m = 0.0f;
        for (int i = 0; i < N; i++) m += dice[i][tid];
        mean_c[tid] = m / (float)N;
    }
    __syncthreads();
    if (tid == 0) {
        float t = 0.0f;
#pragma unroll
        for (int c = 0; c < NCLS; c++) t += w[c] * mean_c[c];
        total_s = t;
    }
    __syncthreads();

    for (int i = tid; i < out_size; i += 256) {
        float v;
        if (out_size >= NCLS + 1) {
            v = (i == 0) ? total_s : (i <= NCLS ? mean_c[i - 1] : 0.0f);
        } else if (out_size == NCLS) {
            v = mean_c[i];
        } else {
            v = (i == 0) ? total_s : (i - 1 < NCLS ? mean_c[i - 1] : 0.0f);
        }
        out[i] = v;
    }

    __threadfence();
    __syncthreads();
    if (tid == 0) g_done = 0u;  // replay-safe reset
}

extern "C" void kernel_launch(void* const* d_in, const int* in_sizes, int n_in,
                              void* d_out, int out_size) {
    const int* inB = (const int*)d_in[0];
    const int* tgB = (const int*)d_in[1];
    const float* w = (const float*)d_in[2];
    float* out = (float*)d_out;

    int N = in_sizes[0] / PIX;
    if (N < 1) N = 1;
    if (N > MAXN) N = MAXN;

    dim3 grid(GX, N);
    k_dice_fused<<<grid, 256>>>(inB, tgB, w, out, out_size, N);
}